// round 16
// baseline (speedup 1.0000x reference)
#include <cuda_runtime.h>
#include <cuda_fp16.h>
#include <math.h>

// Problem constants (from reference)
#define N_NODES_MAX 100000
#define E_MAX       1600000
#define IN_C 128
#define H1   71
#define H2   82
#define NP1  72   // H1 padded (18 quads / 9 half-uint4 chunks)

// ------------------- device scratch (static, no allocation) -------------------
__device__ int   g_is64;
__device__ int   g_deg[N_NODES_MAX];
__device__ float g_dinv[N_NODES_MAX];
__device__ int   g_rowoff[N_NODES_MAX + 1];
__device__ int   g_cursor[N_NODES_MAX];
__device__ int   g_csr[E_MAX];
__device__ int   g_src[E_MAX];
__device__ int   g_dst[E_MAX];
__device__ int   g_bsum[256];
__device__ float g_w23[NP1];   // W2 @ W3 (padded with zeros)
__device__ float g_beta;       // b2 . W3
__device__ __align__(16) __half g_bufH[(size_t)N_NODES_MAX * NP1];  // xw rows (fp16)
__device__ float g_v[N_NODES_MAX];   // v = h1 . w23
__device__ float g_t[N_NODES_MAX];   // t = Anorm.v + beta

// ------------------- packed f32x2 helpers -------------------
__device__ __forceinline__ void upk2(float& lo, float& hi, unsigned long long v) {
    asm("mov.b64 {%0, %1}, %2;" : "=f"(lo), "=f"(hi) : "l"(v));
}
#define FMA2(d, a, b, c) \
    asm("fma.rn.f32x2 %0, %1, %2, %3;" : "=l"(d) : "l"(a), "l"(b), "l"(c))

// ------------------- setup kernels -------------------
__global__ void k_init_deg(const int* __restrict__ ei32, int E, int n) {
    int i = blockIdx.x * blockDim.x + threadIdx.x;
    if (i < n) g_deg[i] = 0;
    if (blockIdx.x == 0 && threadIdx.x == 0) {
        // dtype sniff: int64 indices < 1e5 have zero odd words
        int all0 = 1;
        int m = (E > 64) ? 64 : E;
        for (int q = 0; q < m; q++)
            if (ei32[2 * q + 1] != 0) { all0 = 0; break; }
        g_is64 = all0;
    }
}

__global__ void k_deg_count(const void* __restrict__ ei, int E, int n) {
    int i = blockIdx.x * blockDim.x + threadIdx.x;
    if (i < E) {
        int s, d;
        if (g_is64) {
            s = (int)((const long long*)ei)[i];
            d = (int)((const long long*)ei)[(size_t)E + i];
        } else {
            s = ((const int*)ei)[i];
            d = ((const int*)ei)[(size_t)E + i];
        }
        s = min(max(s, 0), n - 1);
        d = min(max(d, 0), n - 1);
        g_src[i] = s;
        g_dst[i] = d;
        atomicAdd(&g_deg[d], 1);
    }
}

// layer 2+3 collapse: w23 = W2 @ W3 (zero-padded), beta = b2 . W3
__global__ void k_w23(const float* __restrict__ W2, const float* __restrict__ W3,
                      const float* __restrict__ b2) {
    __shared__ float w3s[H2];
    int t = threadIdx.x;
    if (t < H2) w3s[t] = W3[t];
    __syncthreads();
    if (t < NP1) {
        float s = 0.0f;
        if (t < H1) {
            const float* r = W2 + (size_t)t * H2;
#pragma unroll 2
            for (int j = 0; j < H2; j++) s = fmaf(r[j], w3s[j], s);
        }
        g_w23[t] = s;
    }
    if (t == 127) {
        float be = 0.0f;
        for (int j = 0; j < H2; j++) be = fmaf(b2[j], w3s[j], be);
        g_beta = be;
    }
}

// pass 1: per-block (1024 elems) sums of deg; also compute dinv.
__global__ void __launch_bounds__(1024) k_scan1(int n) {
    __shared__ int wsum[32];
    int t = threadIdx.x, lane = t & 31, wid = t >> 5;
    int i = blockIdx.x * 1024 + t;
    int v = (i < n) ? g_deg[i] : 0;
    if (i < n) g_dinv[i] = rsqrtf((float)v + 1.0f);
    int x = v;
#pragma unroll
    for (int off = 16; off; off >>= 1) x += __shfl_down_sync(0xffffffffu, x, off);
    if (lane == 0) wsum[wid] = x;
    __syncthreads();
    if (wid == 0) {
        int y = wsum[lane];
#pragma unroll
        for (int off = 16; off; off >>= 1) y += __shfl_down_sync(0xffffffffu, y, off);
        if (lane == 0) g_bsum[blockIdx.x] = y;
    }
}

// pass 2+3 fused: each block computes its own bsum prefix, then local scan.
__global__ void __launch_bounds__(1024) k_scan3(int n, int nb) {
    __shared__ int wsum[32];
    __shared__ int s_base;
    int t = threadIdx.x, lane = t & 31, wid = t >> 5;
    if (wid == 0) {
        int s = 0;
        for (int i = lane; i < blockIdx.x; i += 32) s += g_bsum[i];
#pragma unroll
        for (int off = 16; off; off >>= 1) s += __shfl_down_sync(0xffffffffu, s, off);
        if (lane == 0) s_base = s;
    }
    int i = blockIdx.x * 1024 + t;
    int v = (i < n) ? g_deg[i] : 0;
    int x = v;
#pragma unroll
    for (int off = 1; off < 32; off <<= 1) {
        int y = __shfl_up_sync(0xffffffffu, x, off);
        if (lane >= off) x += y;
    }
    if (lane == 31) wsum[wid] = x;
    __syncthreads();
    if (wid == 0) {
        int w = wsum[lane];
        int xx = w;
#pragma unroll
        for (int off = 1; off < 32; off <<= 1) {
            int y = __shfl_up_sync(0xffffffffu, xx, off);
            if (lane >= off) xx += y;
        }
        wsum[lane] = xx - w;
    }
    __syncthreads();
    int excl = s_base + wsum[wid] + (x - v);
    if (i < n) {
        g_rowoff[i] = excl;
        g_cursor[i] = excl;
    }
    if (i == n - 1) g_rowoff[n] = excl + v;
}

__global__ void k_fill(int E) {
    int i = blockIdx.x * blockDim.x + threadIdx.x;
    if (i < E) {
        int d = g_dst[i];
        int p = atomicAdd(&g_cursor[d], 1);
        g_csr[p] = g_src[i];
    }
}

// ------------------- node-pair-packed GEMM (layer 1) -> fp16 rows ----------------
// g_bufH[node, :NP) = half(X[node,:] @ W).
// f32x2 lanes hold NODE PAIRS: x stored plain fp32 (pairs contiguous), W stored
// duplicated (w,w). Per thread-kk: 4 LDS.128 + 16 FFMA2.
template <int NQ, int TY, int TM, int KREAL, int KLOOP, int LDX,
          int NREAL, int NP, int MAXB>
__global__ void __launch_bounds__(NQ * TY, MAXB)
k_gemm_pipe(const float* __restrict__ X, const float* __restrict__ W, int n) {
    constexpr int KK = 16;
    constexpr int NT = (KLOOP + KK - 1) / KK;
    constexpr int BM = TY * TM;               // 112 nodes (448B row, 16B mult)
    constexpr int THREADS = NQ * TY;
    __shared__ __align__(16) float  xs[2][KK][BM];
    __shared__ __align__(16) float2 wd[2][KK][NP];
    const int tx = threadIdx.x, ty = threadIdx.y;
    const int t = ty * NQ + tx;
    const int node0 = blockIdx.x * BM;

    unsigned long long acc[16];  // acc[4*p + c]: pair p (nodes 2p,2p+1), col c
#pragma unroll
    for (int h = 0; h < 16; h++) acc[h] = 0ull;

    auto load_tile = [&](int tile, int buf) {
        const int k0 = tile * KK;
        // x tile: float4 global loads, scalar transposed stores
        for (int idx = t; idx < BM * (KK / 4); idx += THREADS) {
            int nl = idx >> 2;
            int kq = idx & 3;
            int node = node0 + nl;
            float4 v = make_float4(0.f, 0.f, 0.f, 0.f);
            if (node < n)
                v = *(const float4*)(X + (size_t)node * LDX + k0 + kq * 4);
            xs[buf][kq * 4 + 0][nl] = v.x;
            xs[buf][kq * 4 + 1][nl] = v.y;
            xs[buf][kq * 4 + 2][nl] = v.z;
            xs[buf][kq * 4 + 3][nl] = v.w;
        }
        // W chunk, duplicated (w,w), zero-padded in k and N
        for (int idx = t; idx < KK * NP; idx += THREADS) {
            int kk = idx / NP;
            int c = idx - kk * NP;
            int gk = k0 + kk;
            float w = (gk < KREAL && c < NREAL) ? W[(size_t)gk * NREAL + c] : 0.0f;
            wd[buf][kk][c] = make_float2(w, w);
        }
    };

    load_tile(0, 0);
    __syncthreads();

    for (int tile = 0; tile < NT; tile++) {
        const int cur = tile & 1;
        if (tile + 1 < NT) load_tile(tile + 1, cur ^ 1);
#pragma unroll
        for (int kk = 0; kk < KK; kk++) {
            const float* xrow = &xs[cur][kk][ty * TM];
            ulonglong2 xp01 = *(const ulonglong2*)(xrow);      // pairs 0,1 (nodes 0-3)
            ulonglong2 xp23 = *(const ulonglong2*)(xrow + 4);  // pairs 2,3 (nodes 4-7)
            const float2* wrow = &wd[cur][kk][tx * 4];
            ulonglong2 w01 = *(const ulonglong2*)(wrow);       // cols 0,1 (dup)
            ulonglong2 w23 = *(const ulonglong2*)(wrow + 2);   // cols 2,3 (dup)
            FMA2(acc[0],  xp01.x, w01.x, acc[0]);
            FMA2(acc[1],  xp01.x, w01.y, acc[1]);
            FMA2(acc[2],  xp01.x, w23.x, acc[2]);
            FMA2(acc[3],  xp01.x, w23.y, acc[3]);
            FMA2(acc[4],  xp01.y, w01.x, acc[4]);
            FMA2(acc[5],  xp01.y, w01.y, acc[5]);
            FMA2(acc[6],  xp01.y, w23.x, acc[6]);
            FMA2(acc[7],  xp01.y, w23.y, acc[7]);
            FMA2(acc[8],  xp23.x, w01.x, acc[8]);
            FMA2(acc[9],  xp23.x, w01.y, acc[9]);
            FMA2(acc[10], xp23.x, w23.x, acc[10]);
            FMA2(acc[11], xp23.x, w23.y, acc[11]);
            FMA2(acc[12], xp23.y, w01.x, acc[12]);
            FMA2(acc[13], xp23.y, w01.y, acc[13]);
            FMA2(acc[14], xp23.y, w23.x, acc[14]);
            FMA2(acc[15], xp23.y, w23.y, acc[15]);
        }
        __syncthreads();
    }

    // epilogue: unpack node pairs, emit fp16 quads (same coalesced 8B stores)
#pragma unroll
    for (int p = 0; p < 4; p++) {
        float va[4], vb[4];
#pragma unroll
        for (int c = 0; c < 4; c++) upk2(va[c], vb[c], acc[4 * p + c]);
        int na = node0 + ty * TM + 2 * p;
        if (na < n) {
            __half2 h0 = __floats2half2_rn(va[0], va[1]);
            __half2 h1 = __floats2half2_rn(va[2], va[3]);
            *(uint2*)(g_bufH + (size_t)na * NP + tx * 4) =
                make_uint2(*(unsigned*)&h0, *(unsigned*)&h1);
        }
        if (na + 1 < n) {
            __half2 h0 = __floats2half2_rn(vb[0], vb[1]);
            __half2 h1 = __floats2half2_rn(vb[2], vb[3]);
            *(uint2*)(g_bufH + (size_t)(na + 1) * NP + tx * 4) =
                make_uint2(*(unsigned*)&h0, *(unsigned*)&h1);
        }
    }
}

// ------------------- fused gather + relu + gemv (R14 version) --------------------
// v[i] = w23 . relu( dinv_i*(sum_s dinv_s*xw[s,:] + dinv_i*xw[i,:]) + b1 )
// Block = 252 threads = 28 nodes x 9 lanes (8 cols each). Lanes reduce via smem.
__global__ void __launch_bounds__(252)
k_gather_v(const float* __restrict__ b, int n) {
    constexpr int NC = NP1 / 8;          // 9 uint4 chunks per row
    constexpr int NODES = 252 / NC;      // 28 nodes per block
    __shared__ float w23s[NP1];
    __shared__ float vsum[NODES];
    const int tid = threadIdx.x;
    if (tid < NP1) w23s[tid] = g_w23[tid];
    if (tid < NODES) vsum[tid] = 0.0f;
    __syncthreads();

    const int nl = tid / NC;
    const int lane = tid - nl * NC;      // 0..8
    const int node = blockIdx.x * NODES + nl;
    if (node < n) {
        const uint4* __restrict__ xw = (const uint4*)g_bufH;

        float a0[8], a1[8];
#pragma unroll
        for (int j = 0; j < 8; j++) { a0[j] = 0.f; a1[j] = 0.f; }

        auto accum = [&](float* a, float w, uint4 v) {
            const __half2* h = (const __half2*)&v;
#pragma unroll
            for (int q = 0; q < 4; q++) {
                float2 f = __half22float2(h[q]);
                a[2 * q + 0] = fmaf(w, f.x, a[2 * q + 0]);
                a[2 * q + 1] = fmaf(w, f.y, a[2 * q + 1]);
            }
        };

        const int beg = g_rowoff[node];
        const int end = g_rowoff[node + 1];
        int e = beg;
        for (; e + 3 < end; e += 4) {
            int s0 = g_csr[e];
            int s1 = g_csr[e + 1];
            int s2 = g_csr[e + 2];
            int s3 = g_csr[e + 3];
            float w0 = __ldg(&g_dinv[s0]);
            float w1 = __ldg(&g_dinv[s1]);
            float w2 = __ldg(&g_dinv[s2]);
            float w3 = __ldg(&g_dinv[s3]);
            uint4 v0 = __ldg(&xw[(size_t)s0 * NC + lane]);
            uint4 v1 = __ldg(&xw[(size_t)s1 * NC + lane]);
            uint4 v2 = __ldg(&xw[(size_t)s2 * NC + lane]);
            uint4 v3 = __ldg(&xw[(size_t)s3 * NC + lane]);
            accum(a0, w0, v0);
            accum(a1, w1, v1);
            accum(a0, w2, v2);
            accum(a1, w3, v3);
        }
        for (; e < end; e++) {
            int s0 = g_csr[e];
            float w0 = __ldg(&g_dinv[s0]);
            uint4 v0 = __ldg(&xw[(size_t)s0 * NC + lane]);
            accum(a0, w0, v0);
        }
        const float di = g_dinv[node];
        {
            uint4 vi = __ldg(&xw[(size_t)node * NC + lane]);
            accum(a1, di, vi);
        }
        const int c = lane * 8;
        float partial = 0.0f;
#pragma unroll
        for (int j = 0; j < 8; j++) {
            float bv = (c + j < H1) ? __ldg(&b[c + j]) : 0.0f;
            float hv = fmaxf(fmaf(di, a0[j] + a1[j], bv), 0.0f);  // relu(h1)
            partial = fmaf(hv, w23s[c + j], partial);  // w23 pad = 0 kills pad cols
        }
        atomicAdd(&vsum[nl], partial);
    }
    __syncthreads();
    if (tid < NODES) {
        int nd = blockIdx.x * NODES + tid;
        if (nd < n) g_v[nd] = vsum[tid];
    }
}

// ------------------- scalar gather (two phases) -----------------------------------
// PHASE 0: t = Anorm . v + beta      (g_v -> g_t)
// PHASE 1: out = Anorm . t + b[0]    (g_t -> out)
template <int PHASE>
__global__ void __launch_bounds__(256)
k_gather_scalar(const float* __restrict__ b, float* __restrict__ out, int n) {
    const int node = (blockIdx.x * blockDim.x + threadIdx.x) >> 5;
    if (node >= n) return;
    const int lane = threadIdx.x & 31;
    const float* y = (PHASE == 0) ? (const float*)g_v : (const float*)g_t;
    const int beg = g_rowoff[node];
    const int end = g_rowoff[node + 1];
    float acc = 0.0f;
    for (int e = beg + lane; e < end; e += 32) {
        int s = g_csr[e];
        acc = fmaf(__ldg(&g_dinv[s]), __ldg(&y[s]), acc);
    }
#pragma unroll
    for (int off = 16; off; off >>= 1) acc += __shfl_down_sync(0xffffffffu, acc, off);
    if (lane == 0) {
        float di = g_dinv[node];
        float bias = (PHASE == 0) ? g_beta : __ldg(&b[0]);
        float r = di * (acc + di * y[node]) + bias;
        if (PHASE == 0) g_t[node] = r;
        else out[node] = r;
    }
}

// ------------------- launcher: fork CSR build || layer-1 GEMM ---------------------
extern "C" void kernel_launch(void* const* d_in, const int* in_sizes, int n_in,
                              void* d_out, int out_size) {
    const float* x   = (const float*)d_in[0];
    const void*  ei  = d_in[1];
    const float* W1  = (const float*)d_in[2];
    const float* b1  = (const float*)d_in[3];
    const float* W2  = (const float*)d_in[4];
    const float* b2  = (const float*)d_in[5];
    const float* W3  = (const float*)d_in[6];
    const float* b3  = (const float*)d_in[7];
    float*       out = (float*)d_out;

    const int n = in_sizes[0] / IN_C;
    const int E = in_sizes[1] / 2;

    const int TB = 256;
    const int nb_nodes = (n + TB - 1) / TB;
    const int nb_edges = (E + TB - 1) / TB;
    const int nb_warps = (n * 32 + TB - 1) / TB;  // warp per node
    const int nb_scan  = (n + 1023) / 1024;
    const int nb_gemm1 = (n + 111) / 112;  // NQ=18 x TY=14, TM=8 -> BM=112
    const int nb_gathv = (n + 27) / 28;    // 28 nodes per 252-thread block

    // One-time side stream + events (created on the uncaptured correctness call).
    static cudaStream_t sB = nullptr;
    static cudaEvent_t evFork = nullptr, evJoin = nullptr;
    if (sB == nullptr) {
        cudaStreamCreateWithFlags(&sB, cudaStreamNonBlocking);
        cudaEventCreateWithFlags(&evFork, cudaEventDisableTiming);
        cudaEventCreateWithFlags(&evJoin, cudaEventDisableTiming);
    }

    // main: init (zeros deg, sniffs dtype)
    k_init_deg<<<nb_nodes, TB>>>((const int*)ei, E, n);           // 0
    cudaEventRecord(evFork, 0);
    cudaStreamWaitEvent(sB, evFork, 0);

    // side stream: CSR build + w23
    k_deg_count<<<nb_edges, TB, 0, sB>>>(ei, E, n);               // 1
    k_w23<<<1, 128, 0, sB>>>(W2, W3, b2);                         // 2

    // main: layer-1 GEMM (runs alongside CSR branch)
    k_gemm_pipe<18, 14, 8, IN_C, IN_C, IN_C, H1, NP1, 3>
        <<<nb_gemm1, dim3(18, 14)>>>(x, W1, n);                   // 3 <- profiled

    // side stream: scan + fill
    k_scan1<<<nb_scan, 1024, 0, sB>>>(n);                         // 4
    k_scan3<<<nb_scan, 1024, 0, sB>>>(n, nb_scan);                // 5
    k_fill<<<nb_edges, TB, 0, sB>>>(E);                           // 6
    cudaEventRecord(evJoin, sB);

    // join: gathers need both CSR and gemm output
    cudaStreamWaitEvent(0, evJoin, 0);

    // Fused gather+relu+gemv: bufH -> v
    k_gather_v<<<nb_gathv, 252>>>(b1, n);

    // Collapsed layers 2+3 propagation:
    k_gather_scalar<0><<<nb_warps, TB>>>(nullptr, nullptr, n);  // t
    k_gather_scalar<1><<<nb_warps, TB>>>(b3, out, n);           // out
}

// round 17
// speedup vs baseline: 1.1408x; 1.1408x over previous
#include <cuda_runtime.h>
#include <cuda_fp16.h>
#include <math.h>

// Problem constants (from reference)
#define N_NODES_MAX 100000
#define E_MAX       1600000
#define IN_C 128
#define H1   71
#define H2   82
#define NP1  72   // H1 padded (18 quads / 9 half-uint4 chunks)

// ------------------- device scratch (static, no allocation) -------------------
__device__ int   g_is64;
__device__ int   g_deg[N_NODES_MAX];
__device__ float g_dinv[N_NODES_MAX];
__device__ int   g_rowoff[N_NODES_MAX + 1];
__device__ int   g_cursor[N_NODES_MAX];
__device__ int   g_csr[E_MAX];
__device__ int   g_bsum[256];
__device__ float g_w23[NP1];   // W2 @ W3 (padded with zeros)
__device__ float g_beta;       // b2 . W3
__device__ __align__(16) __half g_bufH[(size_t)N_NODES_MAX * NP1];  // xw rows (fp16)
__device__ float g_v[N_NODES_MAX];   // v = h1 . w23
__device__ float g_t[N_NODES_MAX];   // t = Anorm.v + beta

// ------------------- packed f32x2 helpers -------------------
__device__ __forceinline__ void upk2(float& lo, float& hi, unsigned long long v) {
    asm("mov.b64 {%0, %1}, %2;" : "=f"(lo), "=f"(hi) : "l"(v));
}
#define FMA2(d, a, b, c) \
    asm("fma.rn.f32x2 %0, %1, %2, %3;" : "=l"(d) : "l"(a), "l"(b), "l"(c))

// ------------------- setup kernels -------------------
__global__ void k_init_deg(const int* __restrict__ ei32, int E, int n) {
    int i = blockIdx.x * blockDim.x + threadIdx.x;
    if (i < n) g_deg[i] = 0;
    if (blockIdx.x == 0 && threadIdx.x == 0) {
        // dtype sniff: int64 indices < 1e5 have zero odd words
        int all0 = 1;
        int m = (E > 64) ? 64 : E;
        for (int q = 0; q < m; q++)
            if (ei32[2 * q + 1] != 0) { all0 = 0; break; }
        g_is64 = all0;
    }
}

// degree count: reads ONLY the dst half of edge_index
__global__ void k_deg_count(const void* __restrict__ ei, int E, int n) {
    int i = blockIdx.x * blockDim.x + threadIdx.x;
    if (i < E) {
        int d;
        if (g_is64) d = (int)((const long long*)ei)[(size_t)E + i];
        else        d = ((const int*)ei)[(size_t)E + i];
        d = min(max(d, 0), n - 1);
        atomicAdd(&g_deg[d], 1);
    }
}

// layer 2+3 collapse: w23 = W2 @ W3 (zero-padded), beta = b2 . W3
__global__ void k_w23(const float* __restrict__ W2, const float* __restrict__ W3,
                      const float* __restrict__ b2) {
    __shared__ float w3s[H2];
    int t = threadIdx.x;
    if (t < H2) w3s[t] = W3[t];
    __syncthreads();
    if (t < NP1) {
        float s = 0.0f;
        if (t < H1) {
            const float* r = W2 + (size_t)t * H2;
#pragma unroll 2
            for (int j = 0; j < H2; j++) s = fmaf(r[j], w3s[j], s);
        }
        g_w23[t] = s;
    }
    if (t == 127) {
        float be = 0.0f;
        for (int j = 0; j < H2; j++) be = fmaf(b2[j], w3s[j], be);
        g_beta = be;
    }
}

// pass 1: per-block (1024 elems) sums of deg; also compute dinv.
__global__ void __launch_bounds__(1024) k_scan1(int n) {
    __shared__ int wsum[32];
    int t = threadIdx.x, lane = t & 31, wid = t >> 5;
    int i = blockIdx.x * 1024 + t;
    int v = (i < n) ? g_deg[i] : 0;
    if (i < n) g_dinv[i] = rsqrtf((float)v + 1.0f);
    int x = v;
#pragma unroll
    for (int off = 16; off; off >>= 1) x += __shfl_down_sync(0xffffffffu, x, off);
    if (lane == 0) wsum[wid] = x;
    __syncthreads();
    if (wid == 0) {
        int y = wsum[lane];
#pragma unroll
        for (int off = 16; off; off >>= 1) y += __shfl_down_sync(0xffffffffu, y, off);
        if (lane == 0) g_bsum[blockIdx.x] = y;
    }
}

// pass 2+3 fused: each block computes its own bsum prefix, then local scan.
__global__ void __launch_bounds__(1024) k_scan3(int n, int nb) {
    __shared__ int wsum[32];
    __shared__ int s_base;
    int t = threadIdx.x, lane = t & 31, wid = t >> 5;
    if (wid == 0) {
        int s = 0;
        for (int i = lane; i < blockIdx.x; i += 32) s += g_bsum[i];
#pragma unroll
        for (int off = 16; off; off >>= 1) s += __shfl_down_sync(0xffffffffu, s, off);
        if (lane == 0) s_base = s;
    }
    int i = blockIdx.x * 1024 + t;
    int v = (i < n) ? g_deg[i] : 0;
    int x = v;
#pragma unroll
    for (int off = 1; off < 32; off <<= 1) {
        int y = __shfl_up_sync(0xffffffffu, x, off);
        if (lane >= off) x += y;
    }
    if (lane == 31) wsum[wid] = x;
    __syncthreads();
    if (wid == 0) {
        int w = wsum[lane];
        int xx = w;
#pragma unroll
        for (int off = 1; off < 32; off <<= 1) {
            int y = __shfl_up_sync(0xffffffffu, xx, off);
            if (lane >= off) xx += y;
        }
        wsum[lane] = xx - w;
    }
    __syncthreads();
    int excl = s_base + wsum[wid] + (x - v);
    if (i < n) {
        g_rowoff[i] = excl;
        g_cursor[i] = excl;
    }
    if (i == n - 1) g_rowoff[n] = excl + v;
}

// fill: decodes edge_index directly (no staging arrays)
__global__ void k_fill(const void* __restrict__ ei, int E, int n) {
    int i = blockIdx.x * blockDim.x + threadIdx.x;
    if (i < E) {
        int s, d;
        if (g_is64) {
            s = (int)((const long long*)ei)[i];
            d = (int)((const long long*)ei)[(size_t)E + i];
        } else {
            s = ((const int*)ei)[i];
            d = ((const int*)ei)[(size_t)E + i];
        }
        s = min(max(s, 0), n - 1);
        d = min(max(d, 0), n - 1);
        int p = atomicAdd(&g_cursor[d], 1);
        g_csr[p] = s;
    }
}

// ------------------- pipelined register-tiled GEMM (layer 1) -> fp16 rows --------
// g_bufH[node, :NP) = half(X[node,:] @ W). Fork-overlapped with CSR build.
// R14 structure; MAXB=4 to force 64 regs -> 4 CTAs/SM (occ 50%).
template <int NQ, int TY, int TM, int KREAL, int KLOOP, int LDX,
          int NREAL, int NP, int MAXB>
__global__ void __launch_bounds__(NQ * TY, MAXB)
k_gemm_pipe(const float* __restrict__ X, const float* __restrict__ W, int n) {
    constexpr int KK = 16;
    constexpr int NT = (KLOOP + KK - 1) / KK;
    constexpr int BM = TY * TM;
    constexpr int BMP = BM + 2;
    constexpr int THREADS = NQ * TY;
    __shared__ __align__(16) float2 xs2[2][KK][BMP];
    __shared__ __align__(16) float4 ws4[2][KK][NQ];
    const int tx = threadIdx.x, ty = threadIdx.y;
    const int t = ty * NQ + tx;
    const int node0 = blockIdx.x * BM;

    unsigned long long acc[2 * TM];
#pragma unroll
    for (int h = 0; h < 2 * TM; h++) acc[h] = 0ull;

    auto load_tile = [&](int tile, int buf) {
        const int k0 = tile * KK;
        for (int idx = t; idx < BM * (KK / 4); idx += THREADS) {
            int nl = idx >> 2;
            int kq = idx & 3;
            int node = node0 + nl;
            float4 v = make_float4(0.f, 0.f, 0.f, 0.f);
            if (node < n)
                v = *(const float4*)(X + (size_t)node * LDX + k0 + kq * 4);
            xs2[buf][kq * 4 + 0][nl] = make_float2(v.x, v.x);
            xs2[buf][kq * 4 + 1][nl] = make_float2(v.y, v.y);
            xs2[buf][kq * 4 + 2][nl] = make_float2(v.z, v.z);
            xs2[buf][kq * 4 + 3][nl] = make_float2(v.w, v.w);
        }
        for (int idx = t; idx < KK * NQ; idx += THREADS) {
            int kk = idx / NQ;
            int q = idx - kk * NQ;
            int j = q * 4;
            int gk = k0 + kk;
            float4 w = make_float4(0.f, 0.f, 0.f, 0.f);
            if (gk < KREAL) {
                const float* wr = W + (size_t)gk * NREAL;
                if (j + 0 < NREAL) w.x = wr[j + 0];
                if (j + 1 < NREAL) w.y = wr[j + 1];
                if (j + 2 < NREAL) w.z = wr[j + 2];
                if (j + 3 < NREAL) w.w = wr[j + 3];
            }
            ws4[buf][kk][q] = w;
        }
    };

    load_tile(0, 0);
    __syncthreads();

    for (int tile = 0; tile < NT; tile++) {
        const int cur = tile & 1;
        if (tile + 1 < NT) load_tile(tile + 1, cur ^ 1);
#pragma unroll
        for (int kk = 0; kk < KK; kk++) {
            ulonglong2 w = *reinterpret_cast<const ulonglong2*>(&ws4[cur][kk][tx]);
#pragma unroll
            for (int j = 0; j < TM / 2; j++) {
                ulonglong2 xp = *reinterpret_cast<const ulonglong2*>(
                    &xs2[cur][kk][ty * TM + 2 * j]);
                FMA2(acc[4 * j + 0], xp.x, w.x, acc[4 * j + 0]);
                FMA2(acc[4 * j + 1], xp.x, w.y, acc[4 * j + 1]);
                FMA2(acc[4 * j + 2], xp.y, w.x, acc[4 * j + 2]);
                FMA2(acc[4 * j + 3], xp.y, w.y, acc[4 * j + 3]);
            }
        }
        __syncthreads();
    }

#pragma unroll
    for (int m = 0; m < TM; m++) {
        int node = node0 + ty * TM + m;
        if (node < n) {
            float4 o;
            upk2(o.x, o.y, acc[2 * m]);
            upk2(o.z, o.w, acc[2 * m + 1]);
            __half2 h0 = __floats2half2_rn(o.x, o.y);
            __half2 h1 = __floats2half2_rn(o.z, o.w);
            uint2 pk = make_uint2(*(unsigned*)&h0, *(unsigned*)&h1);
            *(uint2*)(g_bufH + (size_t)node * NP1 + tx * 4) = pk;
        }
    }
}

// ------------------- fused gather + relu + gemv (R14 version) --------------------
// v[i] = w23 . relu( dinv_i*(sum_s dinv_s*xw[s,:] + dinv_i*xw[i,:]) + b1 )
// Block = 252 threads = 28 nodes x 9 lanes (8 cols each). Lanes reduce via smem.
__global__ void __launch_bounds__(252)
k_gather_v(const float* __restrict__ b, int n) {
    constexpr int NC = NP1 / 8;          // 9 uint4 chunks per row
    constexpr int NODES = 252 / NC;      // 28 nodes per block
    __shared__ float w23s[NP1];
    __shared__ float vsum[NODES];
    const int tid = threadIdx.x;
    if (tid < NP1) w23s[tid] = g_w23[tid];
    if (tid < NODES) vsum[tid] = 0.0f;
    __syncthreads();

    const int nl = tid / NC;
    const int lane = tid - nl * NC;      // 0..8
    const int node = blockIdx.x * NODES + nl;
    if (node < n) {
        const uint4* __restrict__ xw = (const uint4*)g_bufH;

        float a0[8], a1[8];
#pragma unroll
        for (int j = 0; j < 8; j++) { a0[j] = 0.f; a1[j] = 0.f; }

        auto accum = [&](float* a, float w, uint4 v) {
            const __half2* h = (const __half2*)&v;
#pragma unroll
            for (int q = 0; q < 4; q++) {
                float2 f = __half22float2(h[q]);
                a[2 * q + 0] = fmaf(w, f.x, a[2 * q + 0]);
                a[2 * q + 1] = fmaf(w, f.y, a[2 * q + 1]);
            }
        };

        const int beg = g_rowoff[node];
        const int end = g_rowoff[node + 1];
        int e = beg;
        for (; e + 3 < end; e += 4) {
            int s0 = g_csr[e];
            int s1 = g_csr[e + 1];
            int s2 = g_csr[e + 2];
            int s3 = g_csr[e + 3];
            float w0 = __ldg(&g_dinv[s0]);
            float w1 = __ldg(&g_dinv[s1]);
            float w2 = __ldg(&g_dinv[s2]);
            float w3 = __ldg(&g_dinv[s3]);
            uint4 v0 = __ldg(&xw[(size_t)s0 * NC + lane]);
            uint4 v1 = __ldg(&xw[(size_t)s1 * NC + lane]);
            uint4 v2 = __ldg(&xw[(size_t)s2 * NC + lane]);
            uint4 v3 = __ldg(&xw[(size_t)s3 * NC + lane]);
            accum(a0, w0, v0);
            accum(a1, w1, v1);
            accum(a0, w2, v2);
            accum(a1, w3, v3);
        }
        for (; e < end; e++) {
            int s0 = g_csr[e];
            float w0 = __ldg(&g_dinv[s0]);
            uint4 v0 = __ldg(&xw[(size_t)s0 * NC + lane]);
            accum(a0, w0, v0);
        }
        const float di = g_dinv[node];
        {
            uint4 vi = __ldg(&xw[(size_t)node * NC + lane]);
            accum(a1, di, vi);
        }
        const int c = lane * 8;
        float partial = 0.0f;
#pragma unroll
        for (int j = 0; j < 8; j++) {
            float bv = (c + j < H1) ? __ldg(&b[c + j]) : 0.0f;
            float hv = fmaxf(fmaf(di, a0[j] + a1[j], bv), 0.0f);  // relu(h1)
            partial = fmaf(hv, w23s[c + j], partial);  // w23 pad = 0 kills pad cols
        }
        atomicAdd(&vsum[nl], partial);
    }
    __syncthreads();
    if (tid < NODES) {
        int nd = blockIdx.x * NODES + tid;
        if (nd < n) g_v[nd] = vsum[tid];
    }
}

// ------------------- scalar gather (two phases) -----------------------------------
// PHASE 0: t = Anorm . v + beta      (g_v -> g_t)
// PHASE 1: out = Anorm . t + b[0]    (g_t -> out)
template <int PHASE>
__global__ void __launch_bounds__(256)
k_gather_scalar(const float* __restrict__ b, float* __restrict__ out, int n) {
    const int node = (blockIdx.x * blockDim.x + threadIdx.x) >> 5;
    if (node >= n) return;
    const int lane = threadIdx.x & 31;
    const float* y = (PHASE == 0) ? (const float*)g_v : (const float*)g_t;
    const int beg = g_rowoff[node];
    const int end = g_rowoff[node + 1];
    float acc = 0.0f;
    for (int e = beg + lane; e < end; e += 32) {
        int s = g_csr[e];
        acc = fmaf(__ldg(&g_dinv[s]), __ldg(&y[s]), acc);
    }
#pragma unroll
    for (int off = 16; off; off >>= 1) acc += __shfl_down_sync(0xffffffffu, acc, off);
    if (lane == 0) {
        float di = g_dinv[node];
        float bias = (PHASE == 0) ? g_beta : __ldg(&b[0]);
        float r = di * (acc + di * y[node]) + bias;
        if (PHASE == 0) g_t[node] = r;
        else out[node] = r;
    }
}

// ------------------- launcher: fork CSR build || layer-1 GEMM ---------------------
extern "C" void kernel_launch(void* const* d_in, const int* in_sizes, int n_in,
                              void* d_out, int out_size) {
    const float* x   = (const float*)d_in[0];
    const void*  ei  = d_in[1];
    const float* W1  = (const float*)d_in[2];
    const float* b1  = (const float*)d_in[3];
    const float* W2  = (const float*)d_in[4];
    const float* b2  = (const float*)d_in[5];
    const float* W3  = (const float*)d_in[6];
    const float* b3  = (const float*)d_in[7];
    float*       out = (float*)d_out;

    const int n = in_sizes[0] / IN_C;
    const int E = in_sizes[1] / 2;

    const int TB = 256;
    const int nb_nodes = (n + TB - 1) / TB;
    const int nb_edges = (E + TB - 1) / TB;
    const int nb_warps = (n * 32 + TB - 1) / TB;  // warp per node
    const int nb_scan  = (n + 1023) / 1024;
    const int nb_gemm1 = (n + 111) / 112;  // NQ=18 x TY=14, TM=8 -> BM=112
    const int nb_gathv = (n + 27) / 28;    // 28 nodes per 252-thread block

    // One-time side stream + events (created on the uncaptured correctness call).
    static cudaStream_t sB = nullptr;
    static cudaEvent_t evFork = nullptr, evJoin = nullptr;
    if (sB == nullptr) {
        cudaStreamCreateWithFlags(&sB, cudaStreamNonBlocking);
        cudaEventCreateWithFlags(&evFork, cudaEventDisableTiming);
        cudaEventCreateWithFlags(&evJoin, cudaEventDisableTiming);
    }

    // main: init (zeros deg, sniffs dtype)
    k_init_deg<<<nb_nodes, TB>>>((const int*)ei, E, n);           // 0
    cudaEventRecord(evFork, 0);
    cudaStreamWaitEvent(sB, evFork, 0);

    // side stream: CSR build + w23
    k_deg_count<<<nb_edges, TB, 0, sB>>>(ei, E, n);               // 1
    k_w23<<<1, 128, 0, sB>>>(W2, W3, b2);                         // 2

    // main: layer-1 GEMM (runs alongside CSR branch)
    k_gemm_pipe<18, 14, 8, IN_C, IN_C, IN_C, H1, NP1, 4>
        <<<nb_gemm1, dim3(18, 14)>>>(x, W1, n);                   // 3 <- profiled

    // side stream: scan + fill
    k_scan1<<<nb_scan, 1024, 0, sB>>>(n);                         // 4
    k_scan3<<<nb_scan, 1024, 0, sB>>>(n, nb_scan);                // 5
    k_fill<<<nb_edges, TB, 0, sB>>>(ei, E, n);                    // 6
    cudaEventRecord(evJoin, sB);

    // join: gathers need both CSR and gemm output
    cudaStreamWaitEvent(0, evJoin, 0);

    // Fused gather+relu+gemv: bufH -> v
    k_gather_v<<<nb_gathv, 252>>>(b1, n);

    // Collapsed layers 2+3 propagation:
    k_gather_scalar<0><<<nb_warps, TB>>>(nullptr, nullptr, n);  // t
    k_gather_scalar<1><<<nb_warps, TB>>>(b3, out, n);           // out
}